// round 2
// baseline (speedup 1.0000x reference)
#include <cuda_runtime.h>
#include <cuda_bf16.h>

#define IN_DIM 128
#define HID 32
#define NEG_SLOPE 0.2f
#define MAXN 100000
#define MAXE 1600000
#define SCAN_T 1024

// Scratch (device globals — no allocation allowed)
__device__ float g_h[MAXN * HID];      // current layer node features h = x@W
__device__ float g_el[MAXN];
__device__ float g_er[MAXN];
__device__ float g_agg[MAXN * HID];    // layer-1 aggregation result
__device__ int   g_cnt[MAXN];          // in-degree histogram
__device__ int   g_rowptr[MAXN + 1];   // CSR row pointers (by dst)
__device__ int   g_fill[MAXN];         // scatter cursors
__device__ int   g_csrc[MAXE];         // CSR column indices = src node ids

// ---------------------------------------------------------------------------
__global__ void k_zero_cnt(int N) {
    int i = blockIdx.x * blockDim.x + threadIdx.x;
    if (i < N) g_cnt[i] = 0;
}

__global__ void k_hist(const int* __restrict__ dst, int E) {
    int e = blockIdx.x * blockDim.x + threadIdx.x;
    if (e < E) atomicAdd(&g_cnt[dst[e]], 1);
}

// Single-block exclusive scan of g_cnt -> g_rowptr / g_fill. N up to 100k.
__global__ void k_scan(int N) {
    int tid = threadIdx.x;
    int chunk = (N + SCAN_T - 1) / SCAN_T;
    int lo = tid * chunk;
    int hi = lo + chunk; if (hi > N) hi = N;
    int sum = 0;
    for (int i = lo; i < hi; i++) sum += g_cnt[i];

    // block-wide inclusive scan of per-thread sums
    __shared__ int warpsums[32];
    int lane = tid & 31, wid = tid >> 5;
    int v = sum;
#pragma unroll
    for (int o = 1; o < 32; o <<= 1) {
        int u = __shfl_up_sync(0xffffffffu, v, o);
        if (lane >= o) v += u;
    }
    if (lane == 31) warpsums[wid] = v;
    __syncthreads();
    if (wid == 0) {
        int w = warpsums[lane];
#pragma unroll
        for (int o = 1; o < 32; o <<= 1) {
            int u = __shfl_up_sync(0xffffffffu, w, o);
            if (lane >= o) w += u;
        }
        warpsums[lane] = w;
    }
    __syncthreads();
    int excl = v - sum + (wid > 0 ? warpsums[wid - 1] : 0);

    int run = excl;
    for (int i = lo; i < hi; i++) {
        g_rowptr[i] = run;
        g_fill[i] = run;
        run += g_cnt[i];
    }
    if (tid == SCAN_T - 1) g_rowptr[N] = run;  // last thread's excl+chunk = total
}

__global__ void k_scatter(const int* __restrict__ src, const int* __restrict__ dst,
                          int E) {
    int e = blockIdx.x * blockDim.x + threadIdx.x;
    if (e >= E) return;
    int pos = atomicAdd(&g_fill[dst[e]], 1);
    g_csrc[pos] = src[e];
}

// ---------------------------------------------------------------------------
// Layer-1 GEMM: h = x @ W1 ; el = h@al ; er = h@ar. One warp/node, lane=dim.
__global__ void k_gemm1(const float* __restrict__ x, const float* __restrict__ W,
                        const float* __restrict__ al, const float* __restrict__ ar,
                        int N) {
    __shared__ float Ws[IN_DIM * HID];
    for (int i = threadIdx.x; i < IN_DIM * HID; i += blockDim.x) Ws[i] = W[i];
    __syncthreads();

    int node = (blockIdx.x * blockDim.x + threadIdx.x) >> 5;
    int lane = threadIdx.x & 31;
    if (node >= N) return;

    const float4* xr = (const float4*)(x + (size_t)node * IN_DIM);
    float acc = 0.f;
#pragma unroll
    for (int k4 = 0; k4 < IN_DIM / 4; k4++) {
        float4 xv = xr[k4];
        acc += xv.x * Ws[(k4 * 4 + 0) * HID + lane];
        acc += xv.y * Ws[(k4 * 4 + 1) * HID + lane];
        acc += xv.z * Ws[(k4 * 4 + 2) * HID + lane];
        acc += xv.w * Ws[(k4 * 4 + 3) * HID + lane];
    }
    g_h[node * HID + lane] = acc;

    float vl = acc * al[lane];
    float vr = acc * ar[lane];
#pragma unroll
    for (int o = 16; o; o >>= 1) {
        vl += __shfl_xor_sync(0xffffffffu, vl, o);
        vr += __shfl_xor_sync(0xffffffffu, vr, o);
    }
    if (lane == 0) { g_el[node] = vl; g_er[node] = vr; }
}

// Layer-2 GEMM: hmid = elu(agg + b1); h = hmid @ W2; el, er.
__global__ void k_gemm2(const float* __restrict__ W2, const float* __restrict__ b1,
                        const float* __restrict__ al, const float* __restrict__ ar,
                        int N) {
    __shared__ float Ws[HID * HID];
    for (int i = threadIdx.x; i < HID * HID; i += blockDim.x) Ws[i] = W2[i];
    __syncthreads();

    int node = (blockIdx.x * blockDim.x + threadIdx.x) >> 5;
    int lane = threadIdx.x & 31;
    if (node >= N) return;

    float v = g_agg[node * HID + lane] + b1[lane];
    v = (v > 0.f) ? v : expm1f(v);  // ELU(alpha=1)

    float acc = 0.f;
#pragma unroll
    for (int k = 0; k < HID; k++) {
        acc += __shfl_sync(0xffffffffu, v, k) * Ws[k * HID + lane];
    }
    g_h[node * HID + lane] = acc;

    float vl = acc * al[lane];
    float vr = acc * ar[lane];
#pragma unroll
    for (int o = 16; o; o >>= 1) {
        vl += __shfl_xor_sync(0xffffffffu, vl, o);
        vr += __shfl_xor_sync(0xffffffffu, vr, o);
    }
    if (lane == 0) { g_el[node] = vl; g_er[node] = vr; }
}

// ---------------------------------------------------------------------------
// Fused edge pass (pull model): one warp per dst node. In registers:
//   denom = sum_e exp(lrelu(el[src]+er[dst]))
//   acc   = sum_e exp(..) * h[src][lane]
// out[dst][lane] = acc/denom (+ bias). No atomics, no intermediate edge array.
__global__ void k_agg_csr(float* __restrict__ out, const float* __restrict__ bias,
                          int N) {
    int node = (blockIdx.x * blockDim.x + threadIdx.x) >> 5;
    int lane = threadIdx.x & 31;
    if (node >= N) return;

    int start = g_rowptr[node];
    int end   = g_rowptr[node + 1];
    float erd = g_er[node];

    float acc = 0.f, den = 0.f;
    int i = start;
    // unroll by 2 for MLP
    for (; i + 1 < end; i += 2) {
        int s0 = g_csrc[i], s1 = g_csrc[i + 1];
        float h0 = g_h[s0 * HID + lane];
        float h1 = g_h[s1 * HID + lane];
        float t0 = g_el[s0] + erd;
        float t1 = g_el[s1] + erd;
        t0 = (t0 > 0.f) ? t0 : NEG_SLOPE * t0;
        t1 = (t1 > 0.f) ? t1 : NEG_SLOPE * t1;
        float x0 = expf(t0), x1 = expf(t1);
        acc += x0 * h0 + x1 * h1;
        den += x0 + x1;
    }
    if (i < end) {
        int s0 = g_csrc[i];
        float h0 = g_h[s0 * HID + lane];
        float t0 = g_el[s0] + erd;
        t0 = (t0 > 0.f) ? t0 : NEG_SLOPE * t0;
        float x0 = expf(t0);
        acc += x0 * h0;
        den += x0;
    }

    float r = (end > start) ? acc / den : 0.f;
    if (bias) r += bias[lane];
    out[node * HID + lane] = r;
}

// ---------------------------------------------------------------------------
extern "C" void kernel_launch(void* const* d_in, const int* in_sizes, int n_in,
                              void* d_out, int out_size) {
    const float* features = (const float*)d_in[0];
    const int*   src      = (const int*)d_in[1];
    const int*   dst      = (const int*)d_in[2];
    const float* W1  = (const float*)d_in[3];
    const float* al1 = (const float*)d_in[4];
    const float* ar1 = (const float*)d_in[5];
    const float* b1  = (const float*)d_in[6];
    const float* W2  = (const float*)d_in[7];
    const float* al2 = (const float*)d_in[8];
    const float* ar2 = (const float*)d_in[9];
    const float* b2  = (const float*)d_in[10];
    float* out = (float*)d_out;

    int N = in_sizes[0] / IN_DIM;
    int E = in_sizes[1];

    const int TB = 256;
    int gridNodeWarps = (N * 32 + TB - 1) / TB;  // 1 warp/node
    int gridN = (N + TB - 1) / TB;
    int gridE = (E + TB - 1) / TB;

    float* aggp = nullptr;
    cudaGetSymbolAddress((void**)&aggp, g_agg);

    // ---- CSR build (shared by both layers) ----
    k_zero_cnt<<<gridN, TB>>>(N);
    k_hist<<<gridE, TB>>>(dst, E);
    k_scan<<<1, SCAN_T>>>(N);
    k_scatter<<<gridE, TB>>>(src, dst, E);

    // ---- Layer 1 ----
    k_gemm1<<<gridNodeWarps, TB>>>(features, W1, al1, ar1, N);
    k_agg_csr<<<gridNodeWarps, TB>>>(aggp, nullptr, N);

    // ---- Layer 2 ----
    k_gemm2<<<gridNodeWarps, TB>>>(W2, b1, al2, ar2, N);
    k_agg_csr<<<gridNodeWarps, TB>>>(out, b2, N);
}

// round 3
// speedup vs baseline: 1.5819x; 1.5819x over previous
#include <cuda_runtime.h>
#include <cuda_bf16.h>

#define IN_DIM 128
#define HID 32
#define NEG_SLOPE 0.2f
#define MAXN 100000
#define MAXE 1600000
#define SB 1024          // scan block size

// Scratch (device globals — no allocation allowed)
__device__ float g_h[MAXN * HID];
__device__ float g_el[MAXN];
__device__ float g_er[MAXN];
__device__ float g_agg[MAXN * HID];
__device__ int   g_cnt[MAXN];
__device__ int   g_rowptr[MAXN + 1];
__device__ int   g_fill[MAXN];
__device__ int   g_csrc[MAXE];
__device__ int   g_bsum[(MAXN + SB - 1) / SB + 1];

// ---------------------------------------------------------------------------
__global__ void k_zero_cnt(int N) {
    int i = blockIdx.x * blockDim.x + threadIdx.x;
    if (i < N) g_cnt[i] = 0;
}

__global__ void k_hist(const int* __restrict__ dst, int E) {
    int e = blockIdx.x * blockDim.x + threadIdx.x;
    if (e < E) atomicAdd(&g_cnt[dst[e]], 1);
}

// --- parallel scan: stage 1 — per-block exclusive scan + block totals -------
__device__ __forceinline__ int block_incl_scan(int v, int* warpsums) {
    int lane = threadIdx.x & 31, wid = threadIdx.x >> 5;
#pragma unroll
    for (int o = 1; o < 32; o <<= 1) {
        int u = __shfl_up_sync(0xffffffffu, v, o);
        if (lane >= o) v += u;
    }
    if (lane == 31) warpsums[wid] = v;
    __syncthreads();
    if (wid == 0) {
        int w = (lane < (blockDim.x >> 5)) ? warpsums[lane] : 0;
#pragma unroll
        for (int o = 1; o < 32; o <<= 1) {
            int u = __shfl_up_sync(0xffffffffu, w, o);
            if (lane >= o) w += u;
        }
        warpsums[lane] = w;
    }
    __syncthreads();
    if (wid > 0) v += warpsums[wid - 1];
    return v;
}

__global__ void k_scan1(int N) {
    __shared__ int warpsums[32];
    int i = blockIdx.x * SB + threadIdx.x;
    int v = (i < N) ? g_cnt[i] : 0;
    int incl = block_incl_scan(v, warpsums);
    if (i < N) g_rowptr[i] = incl - v;          // local exclusive
    if (threadIdx.x == SB - 1) g_bsum[blockIdx.x] = incl;  // block total
}

__global__ void k_scan2(int nb) {
    __shared__ int warpsums[32];
    int tid = threadIdx.x;
    int v = (tid < nb) ? g_bsum[tid] : 0;
    int incl = block_incl_scan(v, warpsums);
    if (tid < nb) g_bsum[tid] = incl - v;       // exclusive block offsets
}

__global__ void k_scan3(int N, int E) {
    int i = blockIdx.x * SB + threadIdx.x;
    if (i < N) {
        int r = g_rowptr[i] + g_bsum[blockIdx.x];
        g_rowptr[i] = r;
        g_fill[i] = r;
    }
    if (i == 0) g_rowptr[N] = E;
}

__global__ void k_scatter(const int* __restrict__ src, const int* __restrict__ dst,
                          int E) {
    int e = blockIdx.x * blockDim.x + threadIdx.x;
    if (e >= E) return;
    int pos = atomicAdd(&g_fill[dst[e]], 1);
    g_csrc[pos] = src[e];
}

// ---------------------------------------------------------------------------
// Layer-1 GEMM: h = x @ W1 ; el = h@al ; er = h@ar. One warp/node, lane=dim.
__global__ void k_gemm1(const float* __restrict__ x, const float* __restrict__ W,
                        const float* __restrict__ al, const float* __restrict__ ar,
                        int N) {
    __shared__ float Ws[IN_DIM * HID];
    for (int i = threadIdx.x; i < IN_DIM * HID; i += blockDim.x) Ws[i] = W[i];
    __syncthreads();

    int node = (blockIdx.x * blockDim.x + threadIdx.x) >> 5;
    int lane = threadIdx.x & 31;
    if (node >= N) return;

    const float4* xr = (const float4*)(x + (size_t)node * IN_DIM);
    float acc = 0.f;
#pragma unroll
    for (int k4 = 0; k4 < IN_DIM / 4; k4++) {
        float4 xv = xr[k4];
        acc += xv.x * Ws[(k4 * 4 + 0) * HID + lane];
        acc += xv.y * Ws[(k4 * 4 + 1) * HID + lane];
        acc += xv.z * Ws[(k4 * 4 + 2) * HID + lane];
        acc += xv.w * Ws[(k4 * 4 + 3) * HID + lane];
    }
    g_h[node * HID + lane] = acc;

    float vl = acc * al[lane];
    float vr = acc * ar[lane];
#pragma unroll
    for (int o = 16; o; o >>= 1) {
        vl += __shfl_xor_sync(0xffffffffu, vl, o);
        vr += __shfl_xor_sync(0xffffffffu, vr, o);
    }
    if (lane == 0) { g_el[node] = vl; g_er[node] = vr; }
}

// Layer-2 GEMM: hmid = elu(agg + b1); h = hmid @ W2; el, er.
__global__ void k_gemm2(const float* __restrict__ W2, const float* __restrict__ b1,
                        const float* __restrict__ al, const float* __restrict__ ar,
                        int N) {
    __shared__ float Ws[HID * HID];
    for (int i = threadIdx.x; i < HID * HID; i += blockDim.x) Ws[i] = W2[i];
    __syncthreads();

    int node = (blockIdx.x * blockDim.x + threadIdx.x) >> 5;
    int lane = threadIdx.x & 31;
    if (node >= N) return;

    float v = g_agg[node * HID + lane] + b1[lane];
    v = (v > 0.f) ? v : expm1f(v);  // ELU(alpha=1)

    float acc = 0.f;
#pragma unroll
    for (int k = 0; k < HID; k++) {
        acc += __shfl_sync(0xffffffffu, v, k) * Ws[k * HID + lane];
    }
    g_h[node * HID + lane] = acc;

    float vl = acc * al[lane];
    float vr = acc * ar[lane];
#pragma unroll
    for (int o = 16; o; o >>= 1) {
        vl += __shfl_xor_sync(0xffffffffu, vl, o);
        vr += __shfl_xor_sync(0xffffffffu, vr, o);
    }
    if (lane == 0) { g_el[node] = vl; g_er[node] = vr; }
}

// ---------------------------------------------------------------------------
// Fused pull aggregation, lane-parallel edge batching.
// One warp per dst node. Per batch of up to 32 in-edges:
//   - lanes load 32 src ids coalesced
//   - lanes gather 32 el values + compute 32 expf IN PARALLEL
//   - broadcast (s, ex) via shuffle; 32 coalesced h-row FMA gathers
__global__ void k_agg_csr(float* __restrict__ out, const float* __restrict__ bias,
                          int N) {
    int node = (blockIdx.x * blockDim.x + threadIdx.x) >> 5;
    int lane = threadIdx.x & 31;
    if (node >= N) return;

    int start = g_rowptr[node];
    int end   = g_rowptr[node + 1];
    float erd = g_er[node];

    float acc = 0.f;
    float denp = 0.f;  // per-lane partial denominator

    for (int base = start; base < end; base += 32) {
        int idx = base + lane;
        bool valid = idx < end;
        int s_l = valid ? g_csrc[idx] : 0;
        float ex_l = 0.f;
        if (valid) {
            float t = g_el[s_l] + erd;
            t = (t > 0.f) ? t : NEG_SLOPE * t;
            ex_l = expf(t);
        }
        denp += ex_l;

        int cnt = end - base; if (cnt > 32) cnt = 32;
        int j = 0;
        for (; j + 4 <= cnt; j += 4) {
            int s0 = __shfl_sync(0xffffffffu, s_l, j);
            int s1 = __shfl_sync(0xffffffffu, s_l, j + 1);
            int s2 = __shfl_sync(0xffffffffu, s_l, j + 2);
            int s3 = __shfl_sync(0xffffffffu, s_l, j + 3);
            float x0 = __shfl_sync(0xffffffffu, ex_l, j);
            float x1 = __shfl_sync(0xffffffffu, ex_l, j + 1);
            float x2 = __shfl_sync(0xffffffffu, ex_l, j + 2);
            float x3 = __shfl_sync(0xffffffffu, ex_l, j + 3);
            float h0 = g_h[s0 * HID + lane];
            float h1 = g_h[s1 * HID + lane];
            float h2 = g_h[s2 * HID + lane];
            float h3 = g_h[s3 * HID + lane];
            acc += x0 * h0 + x1 * h1 + x2 * h2 + x3 * h3;
        }
        for (; j < cnt; j++) {
            int s0 = __shfl_sync(0xffffffffu, s_l, j);
            float x0 = __shfl_sync(0xffffffffu, ex_l, j);
            acc += x0 * g_h[s0 * HID + lane];
        }
    }

    // reduce denominator across lanes (same value needed on all lanes)
#pragma unroll
    for (int o = 16; o; o >>= 1)
        denp += __shfl_xor_sync(0xffffffffu, denp, o);

    float r = (end > start) ? acc / denp : 0.f;
    if (bias) r += bias[lane];
    out[node * HID + lane] = r;
}

// ---------------------------------------------------------------------------
extern "C" void kernel_launch(void* const* d_in, const int* in_sizes, int n_in,
                              void* d_out, int out_size) {
    const float* features = (const float*)d_in[0];
    const int*   src      = (const int*)d_in[1];
    const int*   dst      = (const int*)d_in[2];
    const float* W1  = (const float*)d_in[3];
    const float* al1 = (const float*)d_in[4];
    const float* ar1 = (const float*)d_in[5];
    const float* b1  = (const float*)d_in[6];
    const float* W2  = (const float*)d_in[7];
    const float* al2 = (const float*)d_in[8];
    const float* ar2 = (const float*)d_in[9];
    const float* b2  = (const float*)d_in[10];
    float* out = (float*)d_out;

    int N = in_sizes[0] / IN_DIM;
    int E = in_sizes[1];

    const int TB = 256;
    int gridNodeWarps = (N * 32 + TB - 1) / TB;  // 1 warp/node
    int gridN = (N + TB - 1) / TB;
    int gridE = (E + TB - 1) / TB;
    int nb = (N + SB - 1) / SB;                  // scan blocks (<=1024 supported)

    float* aggp = nullptr;
    cudaGetSymbolAddress((void**)&aggp, g_agg);

    // ---- CSR build (shared by both layers) ----
    k_zero_cnt<<<gridN, TB>>>(N);
    k_hist<<<gridE, TB>>>(dst, E);
    k_scan1<<<nb, SB>>>(N);
    k_scan2<<<1, SB>>>(nb);
    k_scan3<<<nb, SB>>>(N, E);
    k_scatter<<<gridE, TB>>>(src, dst, E);

    // ---- Layer 1 ----
    k_gemm1<<<gridNodeWarps, TB>>>(features, W1, al1, ar1, N);
    k_agg_csr<<<gridNodeWarps, TB>>>(aggp, nullptr, N);

    // ---- Layer 2 ----
    k_gemm2<<<gridNodeWarps, TB>>>(W2, b1, al2, ar2, N);
    k_agg_csr<<<gridNodeWarps, TB>>>(out, b2, N);
}

// round 4
// speedup vs baseline: 2.0383x; 1.2885x over previous
#include <cuda_runtime.h>
#include <cuda_bf16.h>

#define IN_DIM 128
#define HID 32
#define NEG_SLOPE 0.2f
#define MAXN 100000
#define MAXE 1600000
#define SB 1024          // scan block size

// Scratch (device globals — no allocation allowed)
__device__ float g_h[MAXN * HID];
__device__ float g_el[MAXN];
__device__ float g_er[MAXN];
__device__ float g_agg[MAXN * HID];
__device__ int   g_cnt[MAXN];
__device__ int   g_rowptr[MAXN + 1];
__device__ int   g_fill[MAXN];
__device__ int   g_csrc[MAXE];
__device__ int   g_bsum[(MAXN + SB - 1) / SB + 1];

// ---------------------------------------------------------------------------
__global__ void k_zero_cnt(int N) {
    int i = blockIdx.x * blockDim.x + threadIdx.x;
    if (i < N) g_cnt[i] = 0;
}

// int4-vectorized histogram
__global__ void k_hist(const int* __restrict__ dst, int E) {
    int i = blockIdx.x * blockDim.x + threadIdx.x;
    int i4 = i * 4;
    if (i4 + 3 < E) {
        int4 d = *(const int4*)(dst + i4);
        atomicAdd(&g_cnt[d.x], 1);
        atomicAdd(&g_cnt[d.y], 1);
        atomicAdd(&g_cnt[d.z], 1);
        atomicAdd(&g_cnt[d.w], 1);
    } else {
        for (int e = i4; e < E; e++) atomicAdd(&g_cnt[dst[e]], 1);
    }
}

// --- parallel scan --------------------------------------------------------
__device__ __forceinline__ int block_incl_scan(int v, int* warpsums) {
    int lane = threadIdx.x & 31, wid = threadIdx.x >> 5;
#pragma unroll
    for (int o = 1; o < 32; o <<= 1) {
        int u = __shfl_up_sync(0xffffffffu, v, o);
        if (lane >= o) v += u;
    }
    if (lane == 31) warpsums[wid] = v;
    __syncthreads();
    if (wid == 0) {
        int w = (lane < (blockDim.x >> 5)) ? warpsums[lane] : 0;
#pragma unroll
        for (int o = 1; o < 32; o <<= 1) {
            int u = __shfl_up_sync(0xffffffffu, w, o);
            if (lane >= o) w += u;
        }
        warpsums[lane] = w;
    }
    __syncthreads();
    if (wid > 0) v += warpsums[wid - 1];
    return v;
}

__global__ void k_scan1(int N) {
    __shared__ int warpsums[32];
    int i = blockIdx.x * SB + threadIdx.x;
    int v = (i < N) ? g_cnt[i] : 0;
    int incl = block_incl_scan(v, warpsums);
    if (i < N) g_rowptr[i] = incl - v;
    if (threadIdx.x == SB - 1) g_bsum[blockIdx.x] = incl;
}

__global__ void k_scan2(int nb) {
    __shared__ int warpsums[32];
    int tid = threadIdx.x;
    int v = (tid < nb) ? g_bsum[tid] : 0;
    int incl = block_incl_scan(v, warpsums);
    if (tid < nb) g_bsum[tid] = incl - v;
}

__global__ void k_scan3(int N, int E) {
    int i = blockIdx.x * SB + threadIdx.x;
    if (i < N) {
        int r = g_rowptr[i] + g_bsum[blockIdx.x];
        g_rowptr[i] = r;
        g_fill[i] = r;
    }
    if (i == 0) g_rowptr[N] = E;
}

// int4-vectorized scatter
__global__ void k_scatter(const int* __restrict__ src, const int* __restrict__ dst,
                          int E) {
    int i = blockIdx.x * blockDim.x + threadIdx.x;
    int i4 = i * 4;
    if (i4 + 3 < E) {
        int4 s = *(const int4*)(src + i4);
        int4 d = *(const int4*)(dst + i4);
        g_csrc[atomicAdd(&g_fill[d.x], 1)] = s.x;
        g_csrc[atomicAdd(&g_fill[d.y], 1)] = s.y;
        g_csrc[atomicAdd(&g_fill[d.z], 1)] = s.z;
        g_csrc[atomicAdd(&g_fill[d.w], 1)] = s.w;
    } else {
        for (int e = i4; e < E; e++)
            g_csrc[atomicAdd(&g_fill[dst[e]], 1)] = src[e];
    }
}

// ---------------------------------------------------------------------------
// Layer-1 GEMM: 4 nodes per warp, transposed padded weights in smem.
// Wt[o][k] = W[k*HID+o], padded row stride 132 -> conflict-free LDS.128.
#define WT_PITCH (IN_DIM + 4)
__global__ void k_gemm1(const float* __restrict__ x, const float* __restrict__ W,
                        const float* __restrict__ al, const float* __restrict__ ar,
                        int N) {
    __shared__ float Wt[HID * WT_PITCH];
    for (int i = threadIdx.x; i < IN_DIM * HID; i += blockDim.x) {
        int k = i / HID, o = i % HID;
        Wt[o * WT_PITCH + k] = W[i];
    }
    __syncthreads();

    int warp = (blockIdx.x * blockDim.x + threadIdx.x) >> 5;
    int lane = threadIdx.x & 31;
    int n0 = warp * 4;
    if (n0 >= N) return;

    const float4* wv = (const float4*)(Wt + lane * WT_PITCH);
    const float4* x0 = (const float4*)(x + (size_t)n0 * IN_DIM);

    float acc0 = 0.f, acc1 = 0.f, acc2 = 0.f, acc3 = 0.f;
    bool v1 = n0 + 1 < N, v2 = n0 + 2 < N, v3 = n0 + 3 < N;

#pragma unroll
    for (int k4 = 0; k4 < IN_DIM / 4; k4++) {
        float4 w = wv[k4];
        float4 a = x0[k4];
        acc0 += a.x * w.x + a.y * w.y + a.z * w.z + a.w * w.w;
        if (v1) {
            float4 b = x0[IN_DIM / 4 + k4];
            acc1 += b.x * w.x + b.y * w.y + b.z * w.z + b.w * w.w;
        }
        if (v2) {
            float4 c = x0[2 * IN_DIM / 4 + k4];
            acc2 += c.x * w.x + c.y * w.y + c.z * w.z + c.w * w.w;
        }
        if (v3) {
            float4 d = x0[3 * IN_DIM / 4 + k4];
            acc3 += d.x * w.x + d.y * w.y + d.z * w.z + d.w * w.w;
        }
    }

    float alv = al[lane], arv = ar[lane];
    float accs[4] = {acc0, acc1, acc2, acc3};
#pragma unroll
    for (int i = 0; i < 4; i++) {
        if (n0 + i >= N) break;
        float a = accs[i];
        g_h[(size_t)(n0 + i) * HID + lane] = a;
        float vl = a * alv, vr = a * arv;
#pragma unroll
        for (int o = 16; o; o >>= 1) {
            vl += __shfl_xor_sync(0xffffffffu, vl, o);
            vr += __shfl_xor_sync(0xffffffffu, vr, o);
        }
        if (lane == 0) { g_el[n0 + i] = vl; g_er[n0 + i] = vr; }
    }
}

// Layer-2 GEMM: hmid = elu(agg + b1); h = hmid @ W2; el, er. 1 warp/node.
__global__ void k_gemm2(const float* __restrict__ W2, const float* __restrict__ b1,
                        const float* __restrict__ al, const float* __restrict__ ar,
                        int N) {
    __shared__ float Ws[HID * HID];
    for (int i = threadIdx.x; i < HID * HID; i += blockDim.x) Ws[i] = W2[i];
    __syncthreads();

    int node = (blockIdx.x * blockDim.x + threadIdx.x) >> 5;
    int lane = threadIdx.x & 31;
    if (node >= N) return;

    float v = g_agg[(size_t)node * HID + lane] + b1[lane];
    v = (v > 0.f) ? v : expm1f(v);  // ELU(alpha=1)

    float acc = 0.f;
#pragma unroll
    for (int k = 0; k < HID; k++) {
        acc += __shfl_sync(0xffffffffu, v, k) * Ws[k * HID + lane];
    }
    g_h[(size_t)node * HID + lane] = acc;

    float vl = acc * al[lane];
    float vr = acc * ar[lane];
#pragma unroll
    for (int o = 16; o; o >>= 1) {
        vl += __shfl_xor_sync(0xffffffffu, vl, o);
        vr += __shfl_xor_sync(0xffffffffu, vr, o);
    }
    if (lane == 0) { g_el[node] = vl; g_er[node] = vr; }
}

// ---------------------------------------------------------------------------
// Fused pull aggregation, (edge-subgroup x dim-quad) lane mapping.
// lane = eg*8 + dl, eg in 0..3 picks one of 4 concurrent edges,
// dl in 0..7 picks a float4 chunk of the 32-dim row.
// Per 8 edges: 4 SHFL + 2 LDG.128 + 8 FMA4 -> high MLP, low issue count.
__global__ void k_agg_csr(float* __restrict__ out, const float* __restrict__ bias,
                          int N) {
    int node = (blockIdx.x * blockDim.x + threadIdx.x) >> 5;
    int lane = threadIdx.x & 31;
    if (node >= N) return;

    int start = g_rowptr[node];
    int end   = g_rowptr[node + 1];
    int deg   = end - start;
    float erd = g_er[node];

    int eg = lane >> 3;   // 0..3
    int dl = lane & 7;    // 0..7

    float4 acc = {0.f, 0.f, 0.f, 0.f};
    float denp = 0.f;

    for (int base = start; base < end; base += 32) {
        int idx = base + lane;
        bool valid = idx < end;
        int s_l = valid ? g_csrc[idx] : 0;
        float ex_l = 0.f;
        if (valid) {
            float t = g_el[s_l] + erd;
            t = (t > 0.f) ? t : NEG_SLOPE * t;
            ex_l = __expf(t);
        }
        denp += ex_l;

        int cnt = end - base; if (cnt > 32) cnt = 32;
        for (int j0 = 0; j0 < cnt; j0 += 8) {
            int jA = j0 + eg, jB = j0 + 4 + eg;  // always < 32
            int   sA = __shfl_sync(0xffffffffu, s_l, jA);
            float xA = __shfl_sync(0xffffffffu, ex_l, jA);
            int   sB = __shfl_sync(0xffffffffu, s_l, jB);
            float xB = __shfl_sync(0xffffffffu, ex_l, jB);
            float4 hA = *(const float4*)(g_h + (size_t)sA * HID + dl * 4);
            float4 hB = *(const float4*)(g_h + (size_t)sB * HID + dl * 4);
            acc.x += xA * hA.x + xB * hB.x;
            acc.y += xA * hA.y + xB * hB.y;
            acc.z += xA * hA.z + xB * hB.z;
            acc.w += xA * hA.w + xB * hB.w;
        }
    }

    // reduce acc over the 4 edge subgroups (xor strides 8, 16)
#pragma unroll
    for (int off = 8; off <= 16; off <<= 1) {
        acc.x += __shfl_xor_sync(0xffffffffu, acc.x, off);
        acc.y += __shfl_xor_sync(0xffffffffu, acc.y, off);
        acc.z += __shfl_xor_sync(0xffffffffu, acc.z, off);
        acc.w += __shfl_xor_sync(0xffffffffu, acc.w, off);
    }
    // full-warp denominator reduce
#pragma unroll
    for (int off = 16; off; off >>= 1)
        denp += __shfl_xor_sync(0xffffffffu, denp, off);

    if (eg == 0) {  // lanes 0..7 write the 32-float row as float4
        float4 r = {0.f, 0.f, 0.f, 0.f};
        if (deg > 0) {
            float inv = 1.f / denp;
            r.x = acc.x * inv; r.y = acc.y * inv;
            r.z = acc.z * inv; r.w = acc.w * inv;
        }
        if (bias) {
            float4 b = *(const float4*)(bias + dl * 4);
            r.x += b.x; r.y += b.y; r.z += b.z; r.w += b.w;
        }
        *(float4*)(out + (size_t)node * HID + dl * 4) = r;
    }
}

// ---------------------------------------------------------------------------
extern "C" void kernel_launch(void* const* d_in, const int* in_sizes, int n_in,
                              void* d_out, int out_size) {
    const float* features = (const float*)d_in[0];
    const int*   src      = (const int*)d_in[1];
    const int*   dst      = (const int*)d_in[2];
    const float* W1  = (const float*)d_in[3];
    const float* al1 = (const float*)d_in[4];
    const float* ar1 = (const float*)d_in[5];
    const float* b1  = (const float*)d_in[6];
    const float* W2  = (const float*)d_in[7];
    const float* al2 = (const float*)d_in[8];
    const float* ar2 = (const float*)d_in[9];
    const float* b2  = (const float*)d_in[10];
    float* out = (float*)d_out;

    int N = in_sizes[0] / IN_DIM;
    int E = in_sizes[1];

    const int TB = 256;
    int gridNodeWarps = (N * 32 + TB - 1) / TB;         // 1 warp/node
    int gridGemm1     = ((N + 3) / 4 * 32 + TB - 1) / TB;  // 4 nodes/warp
    int gridN  = (N + TB - 1) / TB;
    int gridE4 = ((E + 3) / 4 + TB - 1) / TB;
    int nb = (N + SB - 1) / SB;

    float* aggp = nullptr;
    cudaGetSymbolAddress((void**)&aggp, g_agg);

    // ---- CSR build (shared by both layers) ----
    k_zero_cnt<<<gridN, TB>>>(N);
    k_hist<<<gridE4, TB>>>(dst, E);
    k_scan1<<<nb, SB>>>(N);
    k_scan2<<<1, SB>>>(nb);
    k_scan3<<<nb, SB>>>(N, E);
    k_scatter<<<gridE4, TB>>>(src, dst, E);

    // ---- Layer 1 ----
    k_gemm1<<<gridGemm1, TB>>>(features, W1, al1, ar1, N);
    k_agg_csr<<<gridNodeWarps, TB>>>(aggp, nullptr, N);

    // ---- Layer 2 ----
    k_gemm2<<<gridNodeWarps, TB>>>(W2, b1, al2, ar2, N);
    k_agg_csr<<<gridNodeWarps, TB>>>(out, b2, N);
}

// round 5
// speedup vs baseline: 2.1279x; 1.0440x over previous
#include <cuda_runtime.h>
#include <cuda_bf16.h>

#define IN_DIM 128
#define HID 32
#define NEG_SLOPE 0.2f
#define MAXN 100000
#define MAXE 1600000
#define SB 1024
#define TB 256

typedef unsigned long long u64;

// Scratch (device globals — no allocation allowed)
__device__ float g_h[MAXN * HID];
__device__ float g_el[MAXN];
__device__ float g_er[MAXN];
__device__ float g_agg[MAXN * HID];
__device__ int   g_cnt[MAXN];
__device__ int   g_rowptr[MAXN + 1];
__device__ int   g_fill[MAXN];
__device__ int   g_csrc[MAXE];
__device__ int   g_bsum[(MAXN + SB - 1) / SB + 1];

// ---- packed f32x2 helpers (Blackwell FFMA2: only reachable via PTX) -------
__device__ __forceinline__ u64 pk2(float lo, float hi) {
    u64 r; asm("mov.b64 %0, {%1, %2};" : "=l"(r) : "f"(lo), "f"(hi)); return r;
}
__device__ __forceinline__ void fma2(u64& d, u64 a, u64 b) {
    asm("fma.rn.f32x2 %0, %1, %2, %0;" : "+l"(d) : "l"(a), "l"(b));
}
__device__ __forceinline__ float2 upk2(u64 v) {
    float2 f; asm("mov.b64 {%0, %1}, %2;" : "=f"(f.x), "=f"(f.y) : "l"(v)); return f;
}

// ---------------------------------------------------------------------------
// int4-vectorized histogram
__global__ void k_hist(const int* __restrict__ dst, int E) {
    int i = blockIdx.x * blockDim.x + threadIdx.x;
    int i4 = i * 4;
    if (i4 + 3 < E) {
        int4 d = *(const int4*)(dst + i4);
        atomicAdd(&g_cnt[d.x], 1);
        atomicAdd(&g_cnt[d.y], 1);
        atomicAdd(&g_cnt[d.z], 1);
        atomicAdd(&g_cnt[d.w], 1);
    } else {
        for (int e = i4; e < E; e++) atomicAdd(&g_cnt[dst[e]], 1);
    }
}

// --- scan stage 1: per-block exclusive scan + block totals ------------------
__device__ __forceinline__ int block_incl_scan(int v, int* warpsums) {
    int lane = threadIdx.x & 31, wid = threadIdx.x >> 5;
#pragma unroll
    for (int o = 1; o < 32; o <<= 1) {
        int u = __shfl_up_sync(0xffffffffu, v, o);
        if (lane >= o) v += u;
    }
    if (lane == 31) warpsums[wid] = v;
    __syncthreads();
    if (wid == 0) {
        int w = (lane < (int)(blockDim.x >> 5)) ? warpsums[lane] : 0;
#pragma unroll
        for (int o = 1; o < 32; o <<= 1) {
            int u = __shfl_up_sync(0xffffffffu, w, o);
            if (lane >= o) w += u;
        }
        warpsums[lane] = w;
    }
    __syncthreads();
    if (wid > 0) v += warpsums[wid - 1];
    return v;
}

__global__ void k_scan1(int N) {
    __shared__ int warpsums[32];
    int i = blockIdx.x * SB + threadIdx.x;
    int v = (i < N) ? g_cnt[i] : 0;
    int incl = block_incl_scan(v, warpsums);
    if (i < N) g_rowptr[i] = incl - v;
    if (threadIdx.x == SB - 1) g_bsum[blockIdx.x] = incl;
}

// --- scan stage 2 (fused): each block computes its own offset from g_bsum ---
__global__ void k_scan3(int N, int E) {
    __shared__ int s_off;
    int bid = blockIdx.x;
    if (threadIdx.x < 32) {
        int s = 0;
        for (int j = threadIdx.x; j < bid; j += 32) s += g_bsum[j];
#pragma unroll
        for (int o = 16; o; o >>= 1) s += __shfl_xor_sync(0xffffffffu, s, o);
        if (threadIdx.x == 0) s_off = s;
    }
    __syncthreads();
    int i = bid * SB + threadIdx.x;
    if (i < N) {
        int r = g_rowptr[i] + s_off;
        g_rowptr[i] = r;
        g_fill[i] = r;
    }
    if (i == 0) g_rowptr[N] = E;
}

// ---------------------------------------------------------------------------
// Fused scatter + layer-1 GEMM (independent work, one launch).
// Blocks [0, nScat): CSR scatter. Blocks [nScat, ...): gemm1.
#define WT_PITCH (IN_DIM + 4)
__global__ void k_scatter_gemm1(const int* __restrict__ src, const int* __restrict__ dst,
                                int E, const float* __restrict__ x,
                                const float* __restrict__ W,
                                const float* __restrict__ al, const float* __restrict__ ar,
                                int N, int nScat) {
    __shared__ float Wt[HID * WT_PITCH];

    if ((int)blockIdx.x < nScat) {
        // ---- scatter ----
        int i = blockIdx.x * blockDim.x + threadIdx.x;
        int i4 = i * 4;
        if (i4 + 3 < E) {
            int4 s = *(const int4*)(src + i4);
            int4 d = *(const int4*)(dst + i4);
            g_csrc[atomicAdd(&g_fill[d.x], 1)] = s.x;
            g_csrc[atomicAdd(&g_fill[d.y], 1)] = s.y;
            g_csrc[atomicAdd(&g_fill[d.z], 1)] = s.z;
            g_csrc[atomicAdd(&g_fill[d.w], 1)] = s.w;
        } else {
            for (int e = i4; e < E; e++)
                g_csrc[atomicAdd(&g_fill[dst[e]], 1)] = src[e];
        }
        return;
    }

    // ---- gemm1: 4 nodes/warp, transposed padded weights, FFMA2 ----
    for (int i = threadIdx.x; i < IN_DIM * HID; i += blockDim.x) {
        int k = i / HID, o = i % HID;
        Wt[o * WT_PITCH + k] = W[i];
    }
    __syncthreads();

    int warp = ((blockIdx.x - nScat) * blockDim.x + threadIdx.x) >> 5;
    int lane = threadIdx.x & 31;
    int n0 = warp * 4;
    if (n0 >= N) return;

    const float4* wv = (const float4*)(Wt + lane * WT_PITCH);
    const float4* x0 = (const float4*)(x + (size_t)n0 * IN_DIM);
    bool v1 = n0 + 1 < N, v2 = n0 + 2 < N, v3 = n0 + 3 < N;

    u64 a01[4] = {0, 0, 0, 0}, a23[4] = {0, 0, 0, 0};
#pragma unroll
    for (int k4 = 0; k4 < IN_DIM / 4; k4++) {
        float4 w = wv[k4];
        u64 w01 = pk2(w.x, w.y), w23 = pk2(w.z, w.w);
        float4 a = x0[k4];
        fma2(a01[0], pk2(a.x, a.y), w01);
        fma2(a23[0], pk2(a.z, a.w), w23);
        if (v1) {
            float4 b = x0[IN_DIM / 4 + k4];
            fma2(a01[1], pk2(b.x, b.y), w01);
            fma2(a23[1], pk2(b.z, b.w), w23);
        }
        if (v2) {
            float4 c = x0[2 * IN_DIM / 4 + k4];
            fma2(a01[2], pk2(c.x, c.y), w01);
            fma2(a23[2], pk2(c.z, c.w), w23);
        }
        if (v3) {
            float4 d = x0[3 * IN_DIM / 4 + k4];
            fma2(a01[3], pk2(d.x, d.y), w01);
            fma2(a23[3], pk2(d.z, d.w), w23);
        }
    }

    float alv = al[lane], arv = ar[lane];
#pragma unroll
    for (int i = 0; i < 4; i++) {
        if (n0 + i >= N) break;
        float2 p = upk2(a01[i]), q = upk2(a23[i]);
        float acc = (p.x + p.y) + (q.x + q.y);
        g_h[(size_t)(n0 + i) * HID + lane] = acc;
        float vl = acc * alv, vr = acc * arv;
#pragma unroll
        for (int o = 16; o; o >>= 1) {
            vl += __shfl_xor_sync(0xffffffffu, vl, o);
            vr += __shfl_xor_sync(0xffffffffu, vr, o);
        }
        if (lane == 0) { g_el[n0 + i] = vl; g_er[n0 + i] = vr; }
    }
}

// ---------------------------------------------------------------------------
// Layer-2 GEMM: h = hmid @ W2 (hmid already ELU'd in g_agg); el, er.
// 4 nodes/warp, float4 rows, FFMA2.
#define WT2_PITCH (HID + 4)
__global__ void k_gemm2(const float* __restrict__ W2,
                        const float* __restrict__ al, const float* __restrict__ ar,
                        int N) {
    __shared__ float Wt[HID * WT2_PITCH];
    for (int i = threadIdx.x; i < HID * HID; i += blockDim.x) {
        int k = i / HID, o = i % HID;
        Wt[o * WT2_PITCH + k] = W2[i];
    }
    __syncthreads();

    int warp = (blockIdx.x * blockDim.x + threadIdx.x) >> 5;
    int lane = threadIdx.x & 31;
    int n0 = warp * 4;
    if (n0 >= N) return;

    const float4* wv = (const float4*)(Wt + lane * WT2_PITCH);
    const float4* x0 = (const float4*)(g_agg + (size_t)n0 * HID);
    bool v1 = n0 + 1 < N, v2 = n0 + 2 < N, v3 = n0 + 3 < N;

    u64 a01[4] = {0, 0, 0, 0}, a23[4] = {0, 0, 0, 0};
#pragma unroll
    for (int k4 = 0; k4 < HID / 4; k4++) {
        float4 w = wv[k4];
        u64 w01 = pk2(w.x, w.y), w23 = pk2(w.z, w.w);
        float4 a = x0[k4];
        fma2(a01[0], pk2(a.x, a.y), w01);
        fma2(a23[0], pk2(a.z, a.w), w23);
        if (v1) {
            float4 b = x0[HID / 4 + k4];
            fma2(a01[1], pk2(b.x, b.y), w01);
            fma2(a23[1], pk2(b.z, b.w), w23);
        }
        if (v2) {
            float4 c = x0[2 * HID / 4 + k4];
            fma2(a01[2], pk2(c.x, c.y), w01);
            fma2(a23[2], pk2(c.z, c.w), w23);
        }
        if (v3) {
            float4 d = x0[3 * HID / 4 + k4];
            fma2(a01[3], pk2(d.x, d.y), w01);
            fma2(a23[3], pk2(d.z, d.w), w23);
        }
    }

    float alv = al[lane], arv = ar[lane];
#pragma unroll
    for (int i = 0; i < 4; i++) {
        if (n0 + i >= N) break;
        float2 p = upk2(a01[i]), q = upk2(a23[i]);
        float acc = (p.x + p.y) + (q.x + q.y);
        g_h[(size_t)(n0 + i) * HID + lane] = acc;
        float vl = acc * alv, vr = acc * arv;
#pragma unroll
        for (int o = 16; o; o >>= 1) {
            vl += __shfl_xor_sync(0xffffffffu, vl, o);
            vr += __shfl_xor_sync(0xffffffffu, vr, o);
        }
        if (lane == 0) { g_el[n0 + i] = vl; g_er[n0 + i] = vr; }
    }
}

// ---------------------------------------------------------------------------
// Fused pull aggregation, (edge-subgroup x dim-quad) lane mapping + FFMA2.
// Epilogue: out = (acc/den) + bias, optionally ELU'd (layer 1).
__global__ void k_agg_csr(float* __restrict__ out, const float* __restrict__ bias,
                          int do_elu, int N) {
    int node = (blockIdx.x * blockDim.x + threadIdx.x) >> 5;
    int lane = threadIdx.x & 31;
    if (node >= N) return;

    int start = g_rowptr[node];
    int end   = g_rowptr[node + 1];
    int deg   = end - start;
    float erd = g_er[node];

    int eg = lane >> 3;   // 0..3
    int dl = lane & 7;    // 0..7

    u64 acc01 = 0, acc23 = 0;
    float denp = 0.f;

    for (int base = start; base < end; base += 32) {
        int idx = base + lane;
        bool valid = idx < end;
        int s_l = valid ? g_csrc[idx] : 0;
        float ex_l = 0.f;
        if (valid) {
            float t = g_el[s_l] + erd;
            t = (t > 0.f) ? t : NEG_SLOPE * t;
            ex_l = __expf(t);
        }
        denp += ex_l;

        int cnt = end - base; if (cnt > 32) cnt = 32;
        for (int j0 = 0; j0 < cnt; j0 += 8) {
            int jA = j0 + eg, jB = j0 + 4 + eg;
            int   sA = __shfl_sync(0xffffffffu, s_l, jA);
            float xA = __shfl_sync(0xffffffffu, ex_l, jA);
            int   sB = __shfl_sync(0xffffffffu, s_l, jB);
            float xB = __shfl_sync(0xffffffffu, ex_l, jB);
            float4 hA = *(const float4*)(g_h + (size_t)sA * HID + dl * 4);
            float4 hB = *(const float4*)(g_h + (size_t)sB * HID + dl * 4);
            u64 xA2 = pk2(xA, xA), xB2 = pk2(xB, xB);
            fma2(acc01, xA2, pk2(hA.x, hA.y));
            fma2(acc23, xA2, pk2(hA.z, hA.w));
            fma2(acc01, xB2, pk2(hB.x, hB.y));
            fma2(acc23, xB2, pk2(hB.z, hB.w));
        }
    }

    float2 p = upk2(acc01), q = upk2(acc23);
    float4 acc = {p.x, p.y, q.x, q.y};
#pragma unroll
    for (int off = 8; off <= 16; off <<= 1) {
        acc.x += __shfl_xor_sync(0xffffffffu, acc.x, off);
        acc.y += __shfl_xor_sync(0xffffffffu, acc.y, off);
        acc.z += __shfl_xor_sync(0xffffffffu, acc.z, off);
        acc.w += __shfl_xor_sync(0xffffffffu, acc.w, off);
    }
#pragma unroll
    for (int off = 16; off; off >>= 1)
        denp += __shfl_xor_sync(0xffffffffu, denp, off);

    if (eg == 0) {
        float inv = (deg > 0) ? 1.f / denp : 0.f;
        float4 b = *(const float4*)(bias + dl * 4);
        float4 r;
        r.x = acc.x * inv + b.x;
        r.y = acc.y * inv + b.y;
        r.z = acc.z * inv + b.z;
        r.w = acc.w * inv + b.w;
        if (do_elu) {
            r.x = (r.x > 0.f) ? r.x : expm1f(r.x);
            r.y = (r.y > 0.f) ? r.y : expm1f(r.y);
            r.z = (r.z > 0.f) ? r.z : expm1f(r.z);
            r.w = (r.w > 0.f) ? r.w : expm1f(r.w);
        }
        *(float4*)(out + (size_t)node * HID + dl * 4) = r;
    }
}

// ---------------------------------------------------------------------------
extern "C" void kernel_launch(void* const* d_in, const int* in_sizes, int n_in,
                              void* d_out, int out_size) {
    const float* features = (const float*)d_in[0];
    const int*   src      = (const int*)d_in[1];
    const int*   dst      = (const int*)d_in[2];
    const float* W1  = (const float*)d_in[3];
    const float* al1 = (const float*)d_in[4];
    const float* ar1 = (const float*)d_in[5];
    const float* b1  = (const float*)d_in[6];
    const float* W2  = (const float*)d_in[7];
    const float* al2 = (const float*)d_in[8];
    const float* ar2 = (const float*)d_in[9];
    const float* b2  = (const float*)d_in[10];
    float* out = (float*)d_out;

    int N = in_sizes[0] / IN_DIM;
    int E = in_sizes[1];

    int gridNodeWarps = (N * 32 + TB - 1) / TB;             // 1 warp/node
    int gridGemm      = (((N + 3) / 4) * 32 + TB - 1) / TB;  // 4 nodes/warp
    int gridE4 = ((E + 3) / 4 + TB - 1) / TB;
    int nb = (N + SB - 1) / SB;

    float* aggp = nullptr;
    cudaGetSymbolAddress((void**)&aggp, g_agg);
    int* cntp = nullptr;
    cudaGetSymbolAddress((void**)&cntp, g_cnt);

    // ---- CSR build (shared by both layers) + layer-1 GEMM (fused/overlapped)
    cudaMemsetAsync(cntp, 0, (size_t)N * sizeof(int));
    k_hist<<<gridE4, TB>>>(dst, E);
    k_scan1<<<nb, SB>>>(N);
    k_scan3<<<nb, SB>>>(N, E);
    k_scatter_gemm1<<<gridE4 + gridGemm, TB>>>(src, dst, E, features, W1, al1, ar1,
                                               N, gridE4);

    // ---- Layer 1 aggregation (bias + ELU fused into epilogue) ----
    k_agg_csr<<<gridNodeWarps, TB>>>(aggp, b1, 1, N);

    // ---- Layer 2 ----
    k_gemm2<<<gridGemm, TB>>>(W2, al2, ar2, N);
    k_agg_csr<<<gridNodeWarps, TB>>>(out, b2, 0, N);
}